// round 5
// baseline (speedup 1.0000x reference)
#include <cuda_runtime.h>

#define N_NODES 100000
#define N_EDGES 1600000
#define NFEAT   128
#define NHID    64
#define NCLUS   20
#define NBLK_SCAN 98   // ceil(100000/1024)
#define FIXSCALE 8388608.0f   // 2^23

// ---------------- scratch (static device globals; no allocation) -----------
__device__ float              g_support[(size_t)N_NODES * NHID]; // x @ W
__device__ float              g_dinv[N_NODES];                   // rsqrt(deg)
__device__ unsigned long long g_packed[N_NODES];                 // (count<<32)|fixpt(deg)
__device__ int                g_count[N_NODES];                  // in-degree (real edges)
__device__ int                g_off[N_NODES];                    // CSR offsets (excl)
__device__ int                g_cur[N_NODES];                    // bin cursors
__device__ int                g_bsum[NBLK_SCAN];                 // scan partials
__device__ int                g_boff[NBLK_SCAN];
__device__ unsigned long long g_edges[N_EDGES];                  // packed (norm<<32)|src

// packed f32x2 FMA: d = a*b + d  (both lanes)
__device__ __forceinline__ void ffma2(float2& d, const float2 a, const float2 b) {
    asm("fma.rn.f32x2 %0, %1, %2, %0;"
        : "+l"(*(unsigned long long*)&d)
        : "l"(*(const unsigned long long*)&a),
          "l"(*(const unsigned long long*)&b));
}

// ---------------------------------------------------------------------------
// K1: packed = (count=0, deg = 1.0 fixed-point)  (self-loop weight)
// ---------------------------------------------------------------------------
__global__ void k_init() {
    int i = blockIdx.x * blockDim.x + threadIdx.x;
    if (i < N_NODES) g_packed[i] = (unsigned long long)(unsigned)FIXSCALE;
}

// ---------------------------------------------------------------------------
// K2: one 64-bit RED per edge: count++ (hi), deg += w (lo, 2^23 fixed point)
// ---------------------------------------------------------------------------
__global__ void k_deg(const int* __restrict__ ei, const float* __restrict__ ew) {
    int e = blockIdx.x * blockDim.x + threadIdx.x;
    if (e >= N_EDGES) return;
    int d = ei[N_EDGES + e];
    unsigned wfix = __float2uint_rn(ew[e] * FIXSCALE);
    atomicAdd(&g_packed[d], (1ULL << 32) | (unsigned long long)wfix);
}

// ---------------------------------------------------------------------------
// K3a: unpack (dinv=rsqrt(deg), count) + block-level exclusive scan of count
// ---------------------------------------------------------------------------
__global__ void k_scan1() {
    __shared__ int sm[1024];
    int i = blockIdx.x * 1024 + threadIdx.x;
    int v = 0;
    if (i < N_NODES) {
        unsigned long long p = g_packed[i];
        v = (int)(p >> 32);
        g_count[i] = v;
        g_dinv[i] = rsqrtf((float)(unsigned)p * (1.0f / FIXSCALE));
    }
    sm[threadIdx.x] = v;
    __syncthreads();
    for (int off = 1; off < 1024; off <<= 1) {
        int t = (threadIdx.x >= off) ? sm[threadIdx.x - off] : 0;
        __syncthreads();
        sm[threadIdx.x] += t;
        __syncthreads();
    }
    if (i < N_NODES) g_off[i] = sm[threadIdx.x] - v;      // exclusive
    if (threadIdx.x == 1023) g_bsum[blockIdx.x] = sm[1023];
}

__global__ void k_scan2() {
    __shared__ int sm[128];
    int t = threadIdx.x;
    int v = (t < NBLK_SCAN) ? g_bsum[t] : 0;
    sm[t] = v;
    __syncthreads();
    for (int off = 1; off < 128; off <<= 1) {
        int u = (t >= off) ? sm[t - off] : 0;
        __syncthreads();
        sm[t] += u;
        __syncthreads();
    }
    if (t < NBLK_SCAN) g_boff[t] = sm[t] - v;             // exclusive
}

__global__ void k_scan3() {
    int i = blockIdx.x * 1024 + threadIdx.x;
    if (i < N_NODES) {
        int o = g_off[i] + g_boff[blockIdx.x];
        g_off[i] = o;
        g_cur[i] = o;
    }
}

// ---------------------------------------------------------------------------
// K4: bin-fill — place (src, norm) of each edge into its dst bin
// ---------------------------------------------------------------------------
__global__ void k_binfill(const int* __restrict__ ei, const float* __restrict__ ew) {
    int e = blockIdx.x * blockDim.x + threadIdx.x;
    if (e >= N_EDGES) return;
    int s = ei[e];
    int d = ei[N_EDGES + e];
    float nrm = g_dinv[s] * ew[e] * g_dinv[d];
    int pos = atomicAdd(&g_cur[d], 1);
    g_edges[pos] = ((unsigned long long)__float_as_uint(nrm) << 32) | (unsigned)s;
}

// ---------------------------------------------------------------------------
// K5: support = x @ W  (100000x128 @ 128x64)
// 128-row x 64-col block, 256 threads, 4x8 thread tile, packed f32x2 FMA.
// ---------------------------------------------------------------------------
#define GEMM_ROWS 128
#define GEMM_PAD  132
#define GEMM_SMEM ((NFEAT * NHID + GEMM_ROWS * GEMM_PAD) * 4)

__global__ void k_gemm(const float* __restrict__ x, const float* __restrict__ W) {
    extern __shared__ float sm[];
    float* sW = sm;                    // [128][64]
    float* sX = sm + NFEAT * NHID;     // [128][132]

    int tid  = threadIdx.x;
    int row0 = blockIdx.x * GEMM_ROWS;

    {   // W: 8192 floats = 2048 float4
        const float4* W4 = (const float4*)W;
        float4* sW4 = (float4*)sW;
#pragma unroll
        for (int i = 0; i < 8; i++) sW4[tid + 256 * i] = W4[tid + 256 * i];
    }
    // x tile: 128 rows x 32 float4
    for (int i = tid; i < GEMM_ROWS * 32; i += 256) {
        int r = i >> 5, c4 = i & 31;
        int gr = row0 + r;
        float4 v = make_float4(0.f, 0.f, 0.f, 0.f);
        if (gr < N_NODES) v = ((const float4*)(x + (size_t)gr * NFEAT))[c4];
        *(float4*)&sX[r * GEMM_PAD + c4 * 4] = v;
    }
    __syncthreads();

    int ty = tid >> 3;   // 0..31 -> rows ty*4..+3
    int tx = tid & 7;    // 0..7  -> cols tx*8..+7

    float2 acc[4][4];
#pragma unroll
    for (int i = 0; i < 4; i++)
#pragma unroll
        for (int c = 0; c < 4; c++) acc[i][c] = make_float2(0.f, 0.f);

#pragma unroll 4
    for (int k = 0; k < NFEAT; k++) {
        float4 w01 = *(const float4*)&sW[k * NHID + tx * 8];
        float4 w23 = *(const float4*)&sW[k * NHID + tx * 8 + 4];
        float2 wv[4] = { make_float2(w01.x, w01.y), make_float2(w01.z, w01.w),
                         make_float2(w23.x, w23.y), make_float2(w23.z, w23.w) };
#pragma unroll
        for (int i = 0; i < 4; i++) {
            float xv = sX[(ty * 4 + i) * GEMM_PAD + k];
            float2 xx = make_float2(xv, xv);
#pragma unroll
            for (int c = 0; c < 4; c++) ffma2(acc[i][c], xx, wv[c]);
        }
    }

#pragma unroll
    for (int i = 0; i < 4; i++) {
        int gr = row0 + ty * 4 + i;
        if (gr < N_NODES) {
            float* p = g_support + (size_t)gr * NHID + tx * 8;
            *(float4*)p       = make_float4(acc[i][0].x, acc[i][0].y, acc[i][1].x, acc[i][1].y);
            *(float4*)(p + 4) = make_float4(acc[i][2].x, acc[i][2].y, acc[i][3].x, acc[i][3].y);
        }
    }
}

// ---------------------------------------------------------------------------
// K6: gather — 16 lanes per node (2 nodes per warp), float4 per lane.
// z[i] = b + dinv[i]^2 * support[i] + sum_e norm_e * support[src_e]
// No atomics.
// ---------------------------------------------------------------------------
__global__ void k_gather(const float* __restrict__ b, float* __restrict__ out) {
    int g   = (blockIdx.x * blockDim.x + threadIdx.x) >> 4;  // node
    int sub = threadIdx.x & 15;                              // 0..15, 4 cols each
    if (g >= N_NODES) return;

    int beg = g_off[g];
    int cnt = g_count[g];

    float di = g_dinv[g];
    float sl = di * di;
    float2 sls = make_float2(sl, sl);

    float4 bv = ((const float4*)b)[sub];
    float4 sv = *(const float4*)(g_support + (size_t)g * NHID + sub * 4);
    float2 acc0 = make_float2(bv.x, bv.y);
    float2 acc1 = make_float2(bv.z, bv.w);
    ffma2(acc0, sls, make_float2(sv.x, sv.y));
    ffma2(acc1, sls, make_float2(sv.z, sv.w));

    for (int base = 0; base < cnt; base += 16) {
        int rem = cnt - base;
        int chunk = rem < 16 ? rem : 16;
        unsigned long long pk = 0;
        if (sub < chunk) pk = g_edges[beg + base + sub];
#pragma unroll 4
        for (int j = 0; j < chunk; j++) {
            unsigned long long pj = __shfl_sync(0xFFFFFFFFu, pk, j, 16);
            int   s = (int)(unsigned)pj;
            float n = __uint_as_float((unsigned)(pj >> 32));
            float2 nn = make_float2(n, n);
            float4 v = *(const float4*)(g_support + (size_t)s * NHID + sub * 4);
            ffma2(acc0, nn, make_float2(v.x, v.y));
            ffma2(acc1, nn, make_float2(v.z, v.w));
        }
    }

    *(float4*)(out + (size_t)g * NHID + sub * 4) =
        make_float4(acc0.x, acc0.y, acc1.x, acc1.y);
}

// ---------------------------------------------------------------------------
// K7: Student-t soft assignment q from z
// ---------------------------------------------------------------------------
__global__ void k_q(const float* __restrict__ mu, float* __restrict__ out) {
    __shared__ float smu[NCLUS * NHID];
    int tid = threadIdx.x;
    for (int i = tid; i < NCLUS * NHID; i += blockDim.x) smu[i] = mu[i];
    __syncthreads();

    int i = blockIdx.x * blockDim.x + tid;
    if (i >= N_NODES) return;

    float zv[NHID];
    const float4* zp = (const float4*)(out + (size_t)i * NHID);
#pragma unroll
    for (int j = 0; j < NHID / 4; j++) {
        float4 a = zp[j];
        zv[4 * j + 0] = a.x; zv[4 * j + 1] = a.y;
        zv[4 * j + 2] = a.z; zv[4 * j + 3] = a.w;
    }

    float d2[NCLUS];
#pragma unroll
    for (int k = 0; k < NCLUS; k++) d2[k] = 0.f;

#pragma unroll
    for (int h = 0; h < NHID; h++) {
        float zh = zv[h];
#pragma unroll
        for (int k = 0; k < NCLUS; k++) {
            float df = zh - smu[k * NHID + h];
            d2[k] = fmaf(df, df, d2[k]);
        }
    }

    float p[NCLUS];
    float sum = 0.f;
#pragma unroll
    for (int k = 0; k < NCLUS; k++) {
        float q = 1.f / (1.f + d2[k] * 5.0f + 1e-8f);   // d2/ALPHA, ALPHA=0.2
        float v = 0.5f * powf(q, 1.2f);                 // q^(alpha+1) / 2
        p[k] = v;
        sum += v;
    }
    float inv = 1.f / sum;
    float* qo = out + (size_t)N_NODES * NHID + (size_t)i * NCLUS;
#pragma unroll
    for (int k = 0; k < NCLUS; k++) qo[k] = p[k] * inv;
}

// ---------------------------------------------------------------------------
extern "C" void kernel_launch(void* const* d_in, const int* in_sizes, int n_in,
                              void* d_out, int out_size) {
    const float* x  = (const float*)d_in[0];
    const int*   ei = (const int*)d_in[1];
    const float* ew = (const float*)d_in[2];
    const float* W  = (const float*)d_in[3];
    const float* b  = (const float*)d_in[4];
    const float* mu = (const float*)d_in[5];
    float* out = (float*)d_out;

    cudaFuncSetAttribute(k_gemm, cudaFuncAttributeMaxDynamicSharedMemorySize, GEMM_SMEM);

    k_init<<<(N_NODES + 255) / 256, 256>>>();
    k_deg<<<(N_EDGES + 255) / 256, 256>>>(ei, ew);
    k_scan1<<<NBLK_SCAN, 1024>>>();
    k_scan2<<<1, 128>>>();
    k_scan3<<<NBLK_SCAN, 1024>>>();
    k_binfill<<<(N_EDGES + 255) / 256, 256>>>(ei, ew);
    k_gemm<<<(N_NODES + GEMM_ROWS - 1) / GEMM_ROWS, 256, GEMM_SMEM>>>(x, W);
    k_gather<<<(N_NODES * 16 + 255) / 256, 256>>>(b, out);
    k_q<<<(N_NODES + 255) / 256, 256>>>(mu, out);
}

// round 6
// speedup vs baseline: 1.0862x; 1.0862x over previous
#include <cuda_runtime.h>
#include <cuda_fp16.h>

#define N_NODES 100000
#define N_EDGES 1600000
#define NFEAT   128
#define NHID    64
#define NCLUS   20
#define NBLK_SCAN 98   // ceil(100000/1024)
#define FIXSCALE 8388608.0f   // 2^23

// ---------------- scratch (static device globals; no allocation) -----------
__device__ __half             g_support[(size_t)N_NODES * NHID]; // x @ W (fp16)
__device__ float              g_dinv[N_NODES];                   // rsqrt(deg)
__device__ unsigned long long g_packed[N_NODES];                 // (count<<32)|fixpt(deg)
__device__ int                g_count[N_NODES];                  // in-degree (real edges)
__device__ int                g_off[N_NODES];                    // CSR offsets (excl)
__device__ int                g_cur[N_NODES];                    // bin cursors
__device__ int                g_bsum[NBLK_SCAN];                 // scan partials
__device__ int                g_boff[NBLK_SCAN];
__device__ unsigned long long g_edges[N_EDGES];                  // packed (norm<<32)|src

// packed f32x2 FMA: d = a*b + d  (both lanes)
__device__ __forceinline__ void ffma2(float2& d, const float2 a, const float2 b) {
    asm("fma.rn.f32x2 %0, %1, %2, %0;"
        : "+l"(*(unsigned long long*)&d)
        : "l"(*(const unsigned long long*)&a),
          "l"(*(const unsigned long long*)&b));
}

// ---------------------------------------------------------------------------
// K1: packed = (count=0, deg = 1.0 fixed-point)  (self-loop weight). Reset per call.
// ---------------------------------------------------------------------------
__global__ void k_init() {
    int i = blockIdx.x * blockDim.x + threadIdx.x;
    if (i < N_NODES) g_packed[i] = (unsigned long long)(unsigned)FIXSCALE;
}

// ---------------------------------------------------------------------------
// K2: one 64-bit RED per edge: count++ (hi), deg += w (lo, 2^23 fixed point)
// ---------------------------------------------------------------------------
__global__ void k_deg(const int* __restrict__ ei, const float* __restrict__ ew) {
    int e = blockIdx.x * blockDim.x + threadIdx.x;
    if (e >= N_EDGES) return;
    int d = ei[N_EDGES + e];
    unsigned wfix = __float2uint_rn(ew[e] * FIXSCALE);
    atomicAdd(&g_packed[d], (1ULL << 32) | (unsigned long long)wfix);
}

// ---------------------------------------------------------------------------
// K3: unpack (dinv=rsqrt(deg), count) + block-level exclusive scan of count
// ---------------------------------------------------------------------------
__global__ void k_scan1() {
    __shared__ int sm[1024];
    int i = blockIdx.x * 1024 + threadIdx.x;
    int v = 0;
    if (i < N_NODES) {
        unsigned long long p = g_packed[i];
        v = (int)(p >> 32);
        g_count[i] = v;
        g_dinv[i] = rsqrtf((float)(unsigned)p * (1.0f / FIXSCALE));
    }
    sm[threadIdx.x] = v;
    __syncthreads();
    for (int off = 1; off < 1024; off <<= 1) {
        int t = (threadIdx.x >= off) ? sm[threadIdx.x - off] : 0;
        __syncthreads();
        sm[threadIdx.x] += t;
        __syncthreads();
    }
    if (i < N_NODES) g_off[i] = sm[threadIdx.x] - v;      // exclusive
    if (threadIdx.x == 1023) g_bsum[blockIdx.x] = sm[1023];
}

// ---------------------------------------------------------------------------
// K4: support = x @ W  (100000x128 @ 128x64), fp16 output
// 128-row x 64-col block, 256 threads, 4x8 thread tile, packed f32x2 FMA.
// Placed 4th in launch order so ncu (-s window) profiles it.
// ---------------------------------------------------------------------------
#define GEMM_ROWS 128
#define GEMM_PAD  132
#define GEMM_SMEM ((NFEAT * NHID + GEMM_ROWS * GEMM_PAD) * 4)

__global__ void k_gemm(const float* __restrict__ x, const float* __restrict__ W) {
    extern __shared__ float sm[];
    float* sW = sm;                    // [128][64]
    float* sX = sm + NFEAT * NHID;     // [128][132]

    int tid  = threadIdx.x;
    int row0 = blockIdx.x * GEMM_ROWS;

    {   // W: 8192 floats = 2048 float4
        const float4* W4 = (const float4*)W;
        float4* sW4 = (float4*)sW;
#pragma unroll
        for (int i = 0; i < 8; i++) sW4[tid + 256 * i] = W4[tid + 256 * i];
    }
    // x tile: 128 rows x 32 float4
    for (int i = tid; i < GEMM_ROWS * 32; i += 256) {
        int r = i >> 5, c4 = i & 31;
        int gr = row0 + r;
        float4 v = make_float4(0.f, 0.f, 0.f, 0.f);
        if (gr < N_NODES) v = ((const float4*)(x + (size_t)gr * NFEAT))[c4];
        *(float4*)&sX[r * GEMM_PAD + c4 * 4] = v;
    }
    __syncthreads();

    int ty = tid >> 3;   // 0..31 -> rows ty*4..+3
    int tx = tid & 7;    // 0..7  -> cols tx*8..+7

    float2 acc[4][4];
#pragma unroll
    for (int i = 0; i < 4; i++)
#pragma unroll
        for (int c = 0; c < 4; c++) acc[i][c] = make_float2(0.f, 0.f);

#pragma unroll 4
    for (int k = 0; k < NFEAT; k++) {
        float4 w01 = *(const float4*)&sW[k * NHID + tx * 8];
        float4 w23 = *(const float4*)&sW[k * NHID + tx * 8 + 4];
        float2 wv[4] = { make_float2(w01.x, w01.y), make_float2(w01.z, w01.w),
                         make_float2(w23.x, w23.y), make_float2(w23.z, w23.w) };
#pragma unroll
        for (int i = 0; i < 4; i++) {
            float xv = sX[(ty * 4 + i) * GEMM_PAD + k];
            float2 xx = make_float2(xv, xv);
#pragma unroll
            for (int c = 0; c < 4; c++) ffma2(acc[i][c], xx, wv[c]);
        }
    }

#pragma unroll
    for (int i = 0; i < 4; i++) {
        int gr = row0 + ty * 4 + i;
        if (gr < N_NODES) {
            __half2 h[4];
#pragma unroll
            for (int c = 0; c < 4; c++) h[c] = __floats2half2_rn(acc[i][c].x, acc[i][c].y);
            *(uint4*)(g_support + (size_t)gr * NHID + tx * 8) = *(uint4*)h;
        }
    }
}

__global__ void k_scan2() {
    __shared__ int sm[128];
    int t = threadIdx.x;
    int v = (t < NBLK_SCAN) ? g_bsum[t] : 0;
    sm[t] = v;
    __syncthreads();
    for (int off = 1; off < 128; off <<= 1) {
        int u = (t >= off) ? sm[t - off] : 0;
        __syncthreads();
        sm[t] += u;
        __syncthreads();
    }
    if (t < NBLK_SCAN) g_boff[t] = sm[t] - v;             // exclusive
}

__global__ void k_scan3() {
    int i = blockIdx.x * 1024 + threadIdx.x;
    if (i < N_NODES) {
        int o = g_off[i] + g_boff[blockIdx.x];
        g_off[i] = o;
        g_cur[i] = o;
    }
}

// ---------------------------------------------------------------------------
// K5: bin-fill — place (src, norm) of each edge into its dst bin
// ---------------------------------------------------------------------------
__global__ void k_binfill(const int* __restrict__ ei, const float* __restrict__ ew) {
    int e = blockIdx.x * blockDim.x + threadIdx.x;
    if (e >= N_EDGES) return;
    int s = ei[e];
    int d = ei[N_EDGES + e];
    float nrm = g_dinv[s] * ew[e] * g_dinv[d];
    int pos = atomicAdd(&g_cur[d], 1);
    g_edges[pos] = ((unsigned long long)__float_as_uint(nrm) << 32) | (unsigned)s;
}

// ---------------------------------------------------------------------------
// K6: gather — 16 lanes per node (2 nodes per warp), 4 cols (8B fp16) per lane.
// z[i] = b + dinv[i]^2 * support[i] + sum_e norm_e * support[src_e]
// fp32 accumulate. No atomics.
// ---------------------------------------------------------------------------
__global__ void k_gather(const float* __restrict__ b, float* __restrict__ out) {
    int g   = (blockIdx.x * blockDim.x + threadIdx.x) >> 4;  // node
    int sub = threadIdx.x & 15;                              // 0..15, 4 cols each
    if (g >= N_NODES) return;

    int beg = g_off[g];
    int cnt = g_count[g];

    float di = g_dinv[g];
    float sl = di * di;
    float2 sls = make_float2(sl, sl);

    float4 bv = ((const float4*)b)[sub];
    float2 acc0 = make_float2(bv.x, bv.y);
    float2 acc1 = make_float2(bv.z, bv.w);

    {   // self loop
        uint2 u = *(const uint2*)(g_support + (size_t)g * NHID + sub * 4);
        ffma2(acc0, sls, __half22float2(*(__half2*)&u.x));
        ffma2(acc1, sls, __half22float2(*(__half2*)&u.y));
    }

    for (int base = 0; base < cnt; base += 16) {
        int rem = cnt - base;
        int chunk = rem < 16 ? rem : 16;
        unsigned long long pk = 0;
        if (sub < chunk) pk = g_edges[beg + base + sub];
#pragma unroll 4
        for (int j = 0; j < chunk; j++) {
            unsigned long long pj = __shfl_sync(0xFFFFFFFFu, pk, j, 16);
            int   s = (int)(unsigned)pj;
            float n = __uint_as_float((unsigned)(pj >> 32));
            float2 nn = make_float2(n, n);
            uint2 u = *(const uint2*)(g_support + (size_t)s * NHID + sub * 4);
            ffma2(acc0, nn, __half22float2(*(__half2*)&u.x));
            ffma2(acc1, nn, __half22float2(*(__half2*)&u.y));
        }
    }

    *(float4*)(out + (size_t)g * NHID + sub * 4) =
        make_float4(acc0.x, acc0.y, acc1.x, acc1.y);
}

// ---------------------------------------------------------------------------
// K7: Student-t soft assignment q from z
// ---------------------------------------------------------------------------
__global__ void k_q(const float* __restrict__ mu, float* __restrict__ out) {
    __shared__ float smu[NCLUS * NHID];
    int tid = threadIdx.x;
    for (int i = tid; i < NCLUS * NHID; i += blockDim.x) smu[i] = mu[i];
    __syncthreads();

    int i = blockIdx.x * blockDim.x + tid;
    if (i >= N_NODES) return;

    float zv[NHID];
    const float4* zp = (const float4*)(out + (size_t)i * NHID);
#pragma unroll
    for (int j = 0; j < NHID / 4; j++) {
        float4 a = zp[j];
        zv[4 * j + 0] = a.x; zv[4 * j + 1] = a.y;
        zv[4 * j + 2] = a.z; zv[4 * j + 3] = a.w;
    }

    float d2[NCLUS];
#pragma unroll
    for (int k = 0; k < NCLUS; k++) d2[k] = 0.f;

#pragma unroll
    for (int h = 0; h < NHID; h++) {
        float zh = zv[h];
#pragma unroll
        for (int k = 0; k < NCLUS; k++) {
            float df = zh - smu[k * NHID + h];
            d2[k] = fmaf(df, df, d2[k]);
        }
    }

    float p[NCLUS];
    float sum = 0.f;
#pragma unroll
    for (int k = 0; k < NCLUS; k++) {
        float q = 1.f / (1.f + d2[k] * 5.0f + 1e-8f);   // d2/ALPHA, ALPHA=0.2
        float v = 0.5f * __powf(q, 1.2f);               // q^(alpha+1) / 2  (MUFU path)
        p[k] = v;
        sum += v;
    }
    float inv = 1.f / sum;
    float* qo = out + (size_t)N_NODES * NHID + (size_t)i * NCLUS;
#pragma unroll
    for (int k = 0; k < NCLUS; k++) qo[k] = p[k] * inv;
}

// ---------------------------------------------------------------------------
extern "C" void kernel_launch(void* const* d_in, const int* in_sizes, int n_in,
                              void* d_out, int out_size) {
    const float* x  = (const float*)d_in[0];
    const int*   ei = (const int*)d_in[1];
    const float* ew = (const float*)d_in[2];
    const float* W  = (const float*)d_in[3];
    const float* b  = (const float*)d_in[4];
    const float* mu = (const float*)d_in[5];
    float* out = (float*)d_out;

    cudaFuncSetAttribute(k_gemm, cudaFuncAttributeMaxDynamicSharedMemorySize, GEMM_SMEM);

    k_init<<<(N_NODES + 255) / 256, 256>>>();
    k_deg<<<(N_EDGES + 255) / 256, 256>>>(ei, ew);
    k_scan1<<<NBLK_SCAN, 1024>>>();
    k_gemm<<<(N_NODES + GEMM_ROWS - 1) / GEMM_ROWS, 256, GEMM_SMEM>>>(x, W);  // 4th: profiled
    k_scan2<<<1, 128>>>();
    k_scan3<<<NBLK_SCAN, 1024>>>();
    k_binfill<<<(N_EDGES + 255) / 256, 256>>>(ei, ew);
    k_gather<<<(N_NODES * 16 + 255) / 256, 256>>>(b, out);
    k_q<<<(N_NODES + 255) / 256, 256>>>(mu, out);
}